// round 5
// baseline (speedup 1.0000x reference)
#include <cuda_runtime.h>
#include <math.h>

#define N_TOTAL 32768
#define F_DIM   128
#define EMB     32
#define G_NUM   32
#define N_PER   1024

// Output layout (float32, flattened tuple):
//   [0, 1048576)          xe   (32768 x 32)
//   [OFF_SRC, +33554432)  src  (edge_index_out[0])
//   [OFF_DST, +33554432)  dst  (edge_index_out[1])
//   [OFF_W,   +33554432)  edge_weight
#define OFF_SRC 1048576
#define OFF_DST 34603008
#define OFF_W   68157440

// Scratch (no allocation allowed -> device globals)
__device__ float g_xg[N_TOTAL * EMB];   // normalized embeddings, 4 MB
__device__ float g_sq[N_TOTAL];         // per-row squared norms
__device__ float g_cent[EMB];
__device__ float g_scale;

// ---------------------------------------------------------------------------
// K1: xe = x @ W   (32768x128 @ 128x32)
// ---------------------------------------------------------------------------
__global__ __launch_bounds__(256) void k_gemm(const float* __restrict__ x,
                                              const float* __restrict__ W,
                                              float* __restrict__ xe) {
    __shared__ float xs[32 * 129];
    __shared__ float ws[128 * 32];
    const int tid  = threadIdx.x;
    const int row0 = blockIdx.x * 32;

    const float4* xin = (const float4*)(x + (size_t)row0 * F_DIM);
    for (int f = tid; f < 1024; f += 256) {
        float4 v = xin[f];
        int r = f >> 5;
        int c = (f & 31) * 4;
        xs[r * 129 + c + 0] = v.x;
        xs[r * 129 + c + 1] = v.y;
        xs[r * 129 + c + 2] = v.z;
        xs[r * 129 + c + 3] = v.w;
    }
    for (int f = tid; f < 1024; f += 256)
        ((float4*)ws)[f] = ((const float4*)W)[f];
    __syncthreads();

    const int r  = tid >> 3;
    const int e0 = (tid & 7) * 4;
    float a0 = 0.f, a1 = 0.f, a2 = 0.f, a3 = 0.f;
#pragma unroll
    for (int k = 0; k < 128; k++) {
        float xv = xs[r * 129 + k];
        float4 w4 = *(const float4*)&ws[k * 32 + e0];
        a0 = fmaf(xv, w4.x, a0);
        a1 = fmaf(xv, w4.y, a1);
        a2 = fmaf(xv, w4.z, a2);
        a3 = fmaf(xv, w4.w, a3);
    }
    float4 o; o.x = a0; o.y = a1; o.z = a2; o.w = a3;
    *(float4*)&xe[(size_t)(row0 + r) * EMB + e0] = o;
}

// ---------------------------------------------------------------------------
// K2: centroid = mean(xe[:1024]); scale = 0.9 / max|xe[:1024]-centroid|
// ---------------------------------------------------------------------------
__global__ __launch_bounds__(1024) void k_stats(const float* __restrict__ xe) {
    __shared__ float psum[32][33];
    __shared__ float cent[32];
    __shared__ float wmax[32];
    const int tid = threadIdx.x;
    const int d   = tid & 31;
    const int gsl = tid >> 5;

    float s = 0.f;
    for (int r = gsl; r < N_PER; r += 32)
        s += xe[r * EMB + d];
    psum[d][gsl] = s;
    __syncthreads();

    if (tid < 32) {
        float t = 0.f;
        for (int q = 0; q < 32; q++) t += psum[tid][q];
        float c = t * (1.0f / (float)N_PER);
        cent[tid] = c;
        g_cent[tid] = c;
    }
    __syncthreads();

    const float c = cent[d];
    float m = 0.f;
    for (int r = gsl; r < N_PER; r += 32)
        m = fmaxf(m, fabsf(xe[r * EMB + d] - c));
#pragma unroll
    for (int o = 16; o; o >>= 1)
        m = fmaxf(m, __shfl_xor_sync(0xffffffffu, m, o));
    if ((tid & 31) == 0) wmax[tid >> 5] = m;
    __syncthreads();
    if (tid == 0) {
        float mm = 0.f;
        for (int w = 0; w < 32; w++) mm = fmaxf(mm, wmax[w]);
        g_scale = 0.9f / mm;
    }
}

// ---------------------------------------------------------------------------
// K3: xg = (xe - centroid) * scale ; sq = sum(xg^2). One warp per row.
// 8 warps per 256-thread block -> N_TOTAL/8 = 4096 blocks.
// ---------------------------------------------------------------------------
__global__ __launch_bounds__(256) void k_norm(const float* __restrict__ xe) {
    const int warp = blockIdx.x * 8 + (threadIdx.x >> 5);
    const int lane = threadIdx.x & 31;
    const float c  = g_cent[lane];
    const float sc = g_scale;
    float v = (xe[(size_t)warp * EMB + lane] - c) * sc;
    g_xg[(size_t)warp * EMB + lane] = v;
    float s = v * v;
#pragma unroll
    for (int o = 16; o; o >>= 1)
        s += __shfl_xor_sync(0xffffffffu, s, o);
    if (lane == 0) g_sq[warp] = s;
}

// ---------------------------------------------------------------------------
// K4: pairwise distances -> sigmoid edge weights + edge index pattern.
// One block = one 128x128 (i,j) tile of one graph. K=32 fully in smem
// (k-major, stride 132). 8x8 register tile per thread. float4 epilogue.
// ---------------------------------------------------------------------------
#define BM 128
#define BN 128
#define XST 132

__global__ __launch_bounds__(256, 2) void k_pair(const float* __restrict__ tempp,
                                                 const float* __restrict__ thrp,
                                                 float* __restrict__ out) {
    __shared__ float xsi[32 * XST];
    __shared__ float xsj[32 * XST];
    __shared__ float sqi[BM];
    __shared__ float sqj[BN];

    const int tid = threadIdx.x;
    const int g   = blockIdx.z;
    const int i0  = blockIdx.y * BM;
    const int j0  = blockIdx.x * BN;
    const int gb  = g * N_PER;

    for (int f = tid; f < 1024; f += 256) {
        int row = f & 127;
        int kq  = (f >> 7) * 4;
        float4 vi = *(const float4*)&g_xg[(size_t)(gb + i0 + row) * EMB + kq];
        float4 vj = *(const float4*)&g_xg[(size_t)(gb + j0 + row) * EMB + kq];
        xsi[(kq + 0) * XST + row] = vi.x;
        xsi[(kq + 1) * XST + row] = vi.y;
        xsi[(kq + 2) * XST + row] = vi.z;
        xsi[(kq + 3) * XST + row] = vi.w;
        xsj[(kq + 0) * XST + row] = vj.x;
        xsj[(kq + 1) * XST + row] = vj.y;
        xsj[(kq + 2) * XST + row] = vj.z;
        xsj[(kq + 3) * XST + row] = vj.w;
    }
    if (tid < 128)       sqi[tid]       = g_sq[gb + i0 + tid];
    else                 sqj[tid - 128] = g_sq[gb + j0 + (tid - 128)];
    __syncthreads();

    const int tx = tid & 15;
    const int ty = tid >> 4;

    float acc[8][8];
#pragma unroll
    for (int r = 0; r < 8; r++)
#pragma unroll
        for (int c = 0; c < 8; c++) acc[r][c] = 0.f;

#pragma unroll
    for (int k = 0; k < 32; k++) {
        float4 a0 = *(const float4*)&xsi[k * XST + ty * 8];
        float4 a1 = *(const float4*)&xsi[k * XST + ty * 8 + 4];
        float4 b0 = *(const float4*)&xsj[k * XST + tx * 8];
        float4 b1 = *(const float4*)&xsj[k * XST + tx * 8 + 4];
        float a[8] = {a0.x, a0.y, a0.z, a0.w, a1.x, a1.y, a1.z, a1.w};
        float b[8] = {b0.x, b0.y, b0.z, b0.w, b1.x, b1.y, b1.z, b1.w};
#pragma unroll
        for (int r = 0; r < 8; r++)
#pragma unroll
            for (int c = 0; c < 8; c++)
                acc[r][c] = fmaf(a[r], b[c], acc[r][c]);
    }

    const float T  = *tempp;
    const float th = fabsf(*thrp);
    const float jbase = (float)(gb + j0 + tx * 8);
    const float4 d4lo = make_float4(jbase,       jbase + 1.f, jbase + 2.f, jbase + 3.f);
    const float4 d4hi = make_float4(jbase + 4.f, jbase + 5.f, jbase + 6.f, jbase + 7.f);

#pragma unroll
    for (int r = 0; r < 8; r++) {
        const int i  = i0 + ty * 8 + r;
        const float si = sqi[ty * 8 + r];
        const float iv = (float)(gb + i);
        const size_t rowoff = (size_t)g * ((size_t)N_PER * N_PER)
                            + (size_t)i * N_PER + j0 + tx * 8;
        float w[8];
#pragma unroll
        for (int c = 0; c < 8; c++) {
            float d = si + sqj[tx * 8 + c] - 2.0f * acc[r][c];
            d = fmaxf(d, 0.0f);
            float z = T * (th - d);
            w[c] = 1.0f / (1.0f + __expf(-z));
        }
        const float4 s4 = make_float4(iv, iv, iv, iv);
        *(float4*)&out[OFF_SRC + rowoff]     = s4;
        *(float4*)&out[OFF_SRC + rowoff + 4] = s4;
        *(float4*)&out[OFF_DST + rowoff]     = d4lo;
        *(float4*)&out[OFF_DST + rowoff + 4] = d4hi;
        *(float4*)&out[OFF_W + rowoff]     = make_float4(w[0], w[1], w[2], w[3]);
        *(float4*)&out[OFF_W + rowoff + 4] = make_float4(w[4], w[5], w[6], w[7]);
    }
}

// ---------------------------------------------------------------------------
// Launch
// ---------------------------------------------------------------------------
extern "C" void kernel_launch(void* const* d_in, const int* in_sizes, int n_in,
                              void* d_out, int out_size) {
    const float* x    = (const float*)d_in[0];
    const float* W    = (const float*)d_in[1];
    const float* temp = (const float*)d_in[2];
    const float* thr  = (const float*)d_in[3];
    float* out = (float*)d_out;

    k_gemm <<<N_TOTAL / 32, 256>>>(x, W, out);
    k_stats<<<1, 1024>>>(out);
    k_norm <<<N_TOTAL / 8, 256>>>(out);
    k_pair <<<dim3(N_PER / BN, N_PER / BM, G_NUM), 256>>>(temp, thr, out);
}

// round 10
// speedup vs baseline: 1.2701x; 1.2701x over previous
#include <cuda_runtime.h>
#include <math.h>

#define N_TOTAL 32768
#define F_DIM   128
#define EMB     32
#define G_NUM   32
#define N_PER   1024

// Output layout (float32, flattened tuple):
//   [0, 1048576)          xe   (32768 x 32)
//   [OFF_SRC, +33554432)  src
//   [OFF_DST, +33554432)  dst
//   [OFF_W,   +33554432)  edge_weight
#define OFF_SRC 1048576
#define OFF_DST 34603008
#define OFF_W   68157440

__device__ float g_xg[N_TOTAL * EMB];
__device__ float g_sq[N_TOTAL];
__device__ float g_cent[EMB];
__device__ float g_scale;

// ---------------------------------------------------------------------------
// K1: xe = x @ W   (32768x128 @ 128x32)
// ---------------------------------------------------------------------------
__global__ __launch_bounds__(256) void k_gemm(const float* __restrict__ x,
                                              const float* __restrict__ W,
                                              float* __restrict__ xe) {
    __shared__ float xs[32 * 129];
    __shared__ float ws[128 * 32];
    const int tid  = threadIdx.x;
    const int row0 = blockIdx.x * 32;

    const float4* xin = (const float4*)(x + (size_t)row0 * F_DIM);
    for (int f = tid; f < 1024; f += 256) {
        float4 v = xin[f];
        int r = f >> 5;
        int c = (f & 31) * 4;
        xs[r * 129 + c + 0] = v.x;
        xs[r * 129 + c + 1] = v.y;
        xs[r * 129 + c + 2] = v.z;
        xs[r * 129 + c + 3] = v.w;
    }
    for (int f = tid; f < 1024; f += 256)
        ((float4*)ws)[f] = ((const float4*)W)[f];
    __syncthreads();

    const int r  = tid >> 3;
    const int e0 = (tid & 7) * 4;
    float a0 = 0.f, a1 = 0.f, a2 = 0.f, a3 = 0.f;
#pragma unroll
    for (int k = 0; k < 128; k++) {
        float xv = xs[r * 129 + k];
        float4 w4 = *(const float4*)&ws[k * 32 + e0];
        a0 = fmaf(xv, w4.x, a0);
        a1 = fmaf(xv, w4.y, a1);
        a2 = fmaf(xv, w4.z, a2);
        a3 = fmaf(xv, w4.w, a3);
    }
    float4 o; o.x = a0; o.y = a1; o.z = a2; o.w = a3;
    *(float4*)&xe[(size_t)(row0 + r) * EMB + e0] = o;
}

// ---------------------------------------------------------------------------
// K2: centroid + scale over first graph
// ---------------------------------------------------------------------------
__global__ __launch_bounds__(1024) void k_stats(const float* __restrict__ xe) {
    __shared__ float psum[32][33];
    __shared__ float cent[32];
    __shared__ float wmax[32];
    const int tid = threadIdx.x;
    const int d   = tid & 31;
    const int gsl = tid >> 5;

    float s = 0.f;
    for (int r = gsl; r < N_PER; r += 32)
        s += xe[r * EMB + d];
    psum[d][gsl] = s;
    __syncthreads();

    if (tid < 32) {
        float t = 0.f;
        for (int q = 0; q < 32; q++) t += psum[tid][q];
        float c = t * (1.0f / (float)N_PER);
        cent[tid] = c;
        g_cent[tid] = c;
    }
    __syncthreads();

    const float c = cent[d];
    float m = 0.f;
    for (int r = gsl; r < N_PER; r += 32)
        m = fmaxf(m, fabsf(xe[r * EMB + d] - c));
#pragma unroll
    for (int o = 16; o; o >>= 1)
        m = fmaxf(m, __shfl_xor_sync(0xffffffffu, m, o));
    if ((tid & 31) == 0) wmax[tid >> 5] = m;
    __syncthreads();
    if (tid == 0) {
        float mm = 0.f;
        for (int w = 0; w < 32; w++) mm = fmaxf(mm, wmax[w]);
        g_scale = 0.9f / mm;
    }
}

// ---------------------------------------------------------------------------
// K3: xg = (xe - centroid) * scale ; sq = rowwise norm^2. One warp per row.
// ---------------------------------------------------------------------------
__global__ __launch_bounds__(256) void k_norm(const float* __restrict__ xe) {
    const int warp = blockIdx.x * 8 + (threadIdx.x >> 5);
    const int lane = threadIdx.x & 31;
    const float c  = g_cent[lane];
    const float sc = g_scale;
    float v = (xe[(size_t)warp * EMB + lane] - c) * sc;
    g_xg[(size_t)warp * EMB + lane] = v;
    float s = v * v;
#pragma unroll
    for (int o = 16; o; o >>= 1)
        s += __shfl_xor_sync(0xffffffffu, s, o);
    if (lane == 0) g_sq[warp] = s;
}

// ---------------------------------------------------------------------------
// K4: pairwise -> sigmoid weights + index pattern.
// Block tile 64(i) x 128(j), 256 threads, 8x4 per-thread tile (32 accs),
// 3 CTAs/SM target. k-major smem, a-loads warp-broadcast.
// ---------------------------------------------------------------------------
#define BM 64
#define BN 128
#define ISTR 68     // 64 + 4 pad
#define JSTR 132    // 128 + 4 pad

__global__ __launch_bounds__(256, 3) void k_pair(const float* __restrict__ tempp,
                                                 const float* __restrict__ thrp,
                                                 float* __restrict__ out) {
    __shared__ float xsi[32 * ISTR];
    __shared__ float xsj[32 * JSTR];
    __shared__ float sqi[BM];
    __shared__ float sqj[BN];

    const int tid = threadIdx.x;
    const int g   = blockIdx.z;
    const int i0  = blockIdx.y * BM;
    const int j0  = blockIdx.x * BN;
    const int gb  = g * N_PER;

    // xsi: 64 rows x 32 k  (512 float4 loads)
    for (int f = tid; f < 512; f += 256) {
        int row = f & 63;
        int kq  = (f >> 6) * 4;
        float4 v = *(const float4*)&g_xg[(size_t)(gb + i0 + row) * EMB + kq];
        xsi[(kq + 0) * ISTR + row] = v.x;
        xsi[(kq + 1) * ISTR + row] = v.y;
        xsi[(kq + 2) * ISTR + row] = v.z;
        xsi[(kq + 3) * ISTR + row] = v.w;
    }
    // xsj: 128 rows x 32 k (1024 float4 loads)
    for (int f = tid; f < 1024; f += 256) {
        int row = f & 127;
        int kq  = (f >> 7) * 4;
        float4 v = *(const float4*)&g_xg[(size_t)(gb + j0 + row) * EMB + kq];
        xsj[(kq + 0) * JSTR + row] = v.x;
        xsj[(kq + 1) * JSTR + row] = v.y;
        xsj[(kq + 2) * JSTR + row] = v.z;
        xsj[(kq + 3) * JSTR + row] = v.w;
    }
    if (tid < 64)        sqi[tid]      = g_sq[gb + i0 + tid];
    if (tid >= 128)      sqj[tid - 128] = g_sq[gb + j0 + (tid - 128)];
    __syncthreads();

    const int tx = tid & 31;   // j group of 4  (warp-varying)
    const int ty = tid >> 5;   // i group of 8  (uniform per warp -> broadcast)

    float acc[8][4];
#pragma unroll
    for (int r = 0; r < 8; r++)
#pragma unroll
        for (int c = 0; c < 4; c++) acc[r][c] = 0.f;

#pragma unroll
    for (int k = 0; k < 32; k++) {
        float4 a0 = *(const float4*)&xsi[k * ISTR + ty * 8];
        float4 a1 = *(const float4*)&xsi[k * ISTR + ty * 8 + 4];
        float4 b  = *(const float4*)&xsj[k * JSTR + tx * 4];
        float a[8] = {a0.x, a0.y, a0.z, a0.w, a1.x, a1.y, a1.z, a1.w};
#pragma unroll
        for (int r = 0; r < 8; r++) {
            acc[r][0] = fmaf(a[r], b.x, acc[r][0]);
            acc[r][1] = fmaf(a[r], b.y, acc[r][1]);
            acc[r][2] = fmaf(a[r], b.z, acc[r][2]);
            acc[r][3] = fmaf(a[r], b.w, acc[r][3]);
        }
    }

    const float T  = *tempp;
    const float th = fabsf(*thrp);
    const float s0 = sqj[tx * 4 + 0];
    const float s1 = sqj[tx * 4 + 1];
    const float s2 = sqj[tx * 4 + 2];
    const float s3 = sqj[tx * 4 + 3];
    const float jbase = (float)(gb + j0 + tx * 4);
    const float4 d4 = make_float4(jbase, jbase + 1.f, jbase + 2.f, jbase + 3.f);

#pragma unroll
    for (int r = 0; r < 8; r++) {
        const int i  = i0 + ty * 8 + r;
        const float si = sqi[ty * 8 + r];
        const float iv = (float)(gb + i);
        const size_t rowoff = (size_t)g * ((size_t)N_PER * N_PER)
                            + (size_t)i * N_PER + j0 + tx * 4;
        float d0 = fmaxf(si + s0 - 2.0f * acc[r][0], 0.0f);
        float d1 = fmaxf(si + s1 - 2.0f * acc[r][1], 0.0f);
        float d2 = fmaxf(si + s2 - 2.0f * acc[r][2], 0.0f);
        float d3 = fmaxf(si + s3 - 2.0f * acc[r][3], 0.0f);
        float4 w;
        w.x = 1.0f / (1.0f + __expf(-T * (th - d0)));
        w.y = 1.0f / (1.0f + __expf(-T * (th - d1)));
        w.z = 1.0f / (1.0f + __expf(-T * (th - d2)));
        w.w = 1.0f / (1.0f + __expf(-T * (th - d3)));
        *(float4*)&out[OFF_SRC + rowoff] = make_float4(iv, iv, iv, iv);
        *(float4*)&out[OFF_DST + rowoff] = d4;
        *(float4*)&out[OFF_W   + rowoff] = w;
    }
}

// ---------------------------------------------------------------------------
// Launch
// ---------------------------------------------------------------------------
extern "C" void kernel_launch(void* const* d_in, const int* in_sizes, int n_in,
                              void* d_out, int out_size) {
    const float* x    = (const float*)d_in[0];
    const float* W    = (const float*)d_in[1];
    const float* temp = (const float*)d_in[2];
    const float* thr  = (const float*)d_in[3];
    float* out = (float*)d_out;

    k_gemm <<<N_TOTAL / 32, 256>>>(x, W, out);
    k_stats<<<1, 1024>>>(out);
    k_norm <<<N_TOTAL / 8, 256>>>(out);
    k_pair <<<dim3(N_PER / BN, N_PER / BM, G_NUM), 256>>>(temp, thr, out);
}

// round 11
// speedup vs baseline: 1.3089x; 1.0306x over previous
#include <cuda_runtime.h>
#include <math.h>

#define N_TOTAL 32768
#define F_DIM   128
#define EMB     32
#define G_NUM   32
#define N_PER   1024

// Output layout (float32, flattened tuple):
//   [0, 1048576)          xe   (32768 x 32)
//   [OFF_SRC, +33554432)  src
//   [OFF_DST, +33554432)  dst
//   [OFF_W,   +33554432)  edge_weight
#define OFF_SRC 1048576
#define OFF_DST 34603008
#define OFF_W   68157440

__device__ float g_xg[N_TOTAL * EMB];
__device__ float g_sq[N_TOTAL];
__device__ float g_cent[EMB];
__device__ float g_scale;

// ---------------------------------------------------------------------------
// K1: xe = x @ W   (32768x128 @ 128x32)
// ---------------------------------------------------------------------------
__global__ __launch_bounds__(256) void k_gemm(const float* __restrict__ x,
                                              const float* __restrict__ W,
                                              float* __restrict__ xe) {
    __shared__ float xs[32 * 129];
    __shared__ float ws[128 * 32];
    const int tid  = threadIdx.x;
    const int row0 = blockIdx.x * 32;

    const float4* xin = (const float4*)(x + (size_t)row0 * F_DIM);
    for (int f = tid; f < 1024; f += 256) {
        float4 v = xin[f];
        int r = f >> 5;
        int c = (f & 31) * 4;
        xs[r * 129 + c + 0] = v.x;
        xs[r * 129 + c + 1] = v.y;
        xs[r * 129 + c + 2] = v.z;
        xs[r * 129 + c + 3] = v.w;
    }
    for (int f = tid; f < 1024; f += 256)
        ((float4*)ws)[f] = ((const float4*)W)[f];
    __syncthreads();

    const int r  = tid >> 3;
    const int e0 = (tid & 7) * 4;
    float a0 = 0.f, a1 = 0.f, a2 = 0.f, a3 = 0.f;
#pragma unroll
    for (int k = 0; k < 128; k++) {
        float xv = xs[r * 129 + k];
        float4 w4 = *(const float4*)&ws[k * 32 + e0];
        a0 = fmaf(xv, w4.x, a0);
        a1 = fmaf(xv, w4.y, a1);
        a2 = fmaf(xv, w4.z, a2);
        a3 = fmaf(xv, w4.w, a3);
    }
    float4 o; o.x = a0; o.y = a1; o.z = a2; o.w = a3;
    *(float4*)&xe[(size_t)(row0 + r) * EMB + e0] = o;
}

// ---------------------------------------------------------------------------
// K2: centroid + scale over first graph
// ---------------------------------------------------------------------------
__global__ __launch_bounds__(1024) void k_stats(const float* __restrict__ xe) {
    __shared__ float psum[32][33];
    __shared__ float cent[32];
    __shared__ float wmax[32];
    const int tid = threadIdx.x;
    const int d   = tid & 31;
    const int gsl = tid >> 5;

    float s = 0.f;
    for (int r = gsl; r < N_PER; r += 32)
        s += xe[r * EMB + d];
    psum[d][gsl] = s;
    __syncthreads();

    if (tid < 32) {
        float t = 0.f;
        for (int q = 0; q < 32; q++) t += psum[tid][q];
        float c = t * (1.0f / (float)N_PER);
        cent[tid] = c;
        g_cent[tid] = c;
    }
    __syncthreads();

    const float c = cent[d];
    float m = 0.f;
    for (int r = gsl; r < N_PER; r += 32)
        m = fmaxf(m, fabsf(xe[r * EMB + d] - c));
#pragma unroll
    for (int o = 16; o; o >>= 1)
        m = fmaxf(m, __shfl_xor_sync(0xffffffffu, m, o));
    if ((tid & 31) == 0) wmax[tid >> 5] = m;
    __syncthreads();
    if (tid == 0) {
        float mm = 0.f;
        for (int w = 0; w < 32; w++) mm = fmaxf(mm, wmax[w]);
        g_scale = 0.9f / mm;
    }
}

// ---------------------------------------------------------------------------
// K3: xg = (xe - centroid) * scale ; sq = rowwise norm^2. One warp per row.
// ---------------------------------------------------------------------------
__global__ __launch_bounds__(256) void k_norm(const float* __restrict__ xe) {
    const int warp = blockIdx.x * 8 + (threadIdx.x >> 5);
    const int lane = threadIdx.x & 31;
    const float c  = g_cent[lane];
    const float sc = g_scale;
    float v = (xe[(size_t)warp * EMB + lane] - c) * sc;
    g_xg[(size_t)warp * EMB + lane] = v;
    float s = v * v;
#pragma unroll
    for (int o = 16; o; o >>= 1)
        s += __shfl_xor_sync(0xffffffffu, s, o);
    if (lane == 0) g_sq[warp] = s;
}

// ---------------------------------------------------------------------------
// K4: pairwise -> sigmoid weights + index pattern.
// Block tile 64(i) x 64(j), 256 threads, 4x4 per-thread tile (16 accs),
// target 4 CTAs/SM (~50-56 regs, 18 KB smem). k-major smem, padded stride.
// ---------------------------------------------------------------------------
#define BM 64
#define BN 64
#define STR 68      // 64 + 4 pad

__global__ __launch_bounds__(256, 4) void k_pair(const float* __restrict__ tempp,
                                                 const float* __restrict__ thrp,
                                                 float* __restrict__ out) {
    __shared__ float xsi[32 * STR];
    __shared__ float xsj[32 * STR];
    __shared__ float sqi[BM];
    __shared__ float sqj[BN];

    const int tid = threadIdx.x;
    const int g   = blockIdx.z;
    const int i0  = blockIdx.y * BM;
    const int j0  = blockIdx.x * BN;
    const int gb  = g * N_PER;

    // each tile: 64 rows x 32 k = 512 float4 loads
    for (int f = tid; f < 512; f += 256) {
        int row = f & 63;
        int kq  = (f >> 6) * 4;
        float4 vi = *(const float4*)&g_xg[(size_t)(gb + i0 + row) * EMB + kq];
        float4 vj = *(const float4*)&g_xg[(size_t)(gb + j0 + row) * EMB + kq];
        xsi[(kq + 0) * STR + row] = vi.x;
        xsi[(kq + 1) * STR + row] = vi.y;
        xsi[(kq + 2) * STR + row] = vi.z;
        xsi[(kq + 3) * STR + row] = vi.w;
        xsj[(kq + 0) * STR + row] = vj.x;
        xsj[(kq + 1) * STR + row] = vj.y;
        xsj[(kq + 2) * STR + row] = vj.z;
        xsj[(kq + 3) * STR + row] = vj.w;
    }
    if (tid < 64)                     sqi[tid]      = g_sq[gb + i0 + tid];
    else if (tid < 128)               sqj[tid - 64] = g_sq[gb + j0 + (tid - 64)];
    __syncthreads();

    const int tx = tid & 15;   // j group of 4 (warp-varying, 16 distinct)
    const int ty = tid >> 4;   // i group of 4 (2 distinct per warp -> broadcast)

    float acc[4][4];
#pragma unroll
    for (int r = 0; r < 4; r++)
#pragma unroll
        for (int c = 0; c < 4; c++) acc[r][c] = 0.f;

#pragma unroll
    for (int k = 0; k < 32; k++) {
        float4 a = *(const float4*)&xsi[k * STR + ty * 4];
        float4 b = *(const float4*)&xsj[k * STR + tx * 4];
        acc[0][0] = fmaf(a.x, b.x, acc[0][0]);
        acc[0][1] = fmaf(a.x, b.y, acc[0][1]);
        acc[0][2] = fmaf(a.x, b.z, acc[0][2]);
        acc[0][3] = fmaf(a.x, b.w, acc[0][3]);
        acc[1][0] = fmaf(a.y, b.x, acc[1][0]);
        acc[1][1] = fmaf(a.y, b.y, acc[1][1]);
        acc[1][2] = fmaf(a.y, b.z, acc[1][2]);
        acc[1][3] = fmaf(a.y, b.w, acc[1][3]);
        acc[2][0] = fmaf(a.z, b.x, acc[2][0]);
        acc[2][1] = fmaf(a.z, b.y, acc[2][1]);
        acc[2][2] = fmaf(a.z, b.z, acc[2][2]);
        acc[2][3] = fmaf(a.z, b.w, acc[2][3]);
        acc[3][0] = fmaf(a.w, b.x, acc[3][0]);
        acc[3][1] = fmaf(a.w, b.y, acc[3][1]);
        acc[3][2] = fmaf(a.w, b.z, acc[3][2]);
        acc[3][3] = fmaf(a.w, b.w, acc[3][3]);
    }

    const float T  = *tempp;
    const float th = fabsf(*thrp);
    const float s0 = sqj[tx * 4 + 0];
    const float s1 = sqj[tx * 4 + 1];
    const float s2 = sqj[tx * 4 + 2];
    const float s3 = sqj[tx * 4 + 3];
    const float jbase = (float)(gb + j0 + tx * 4);
    const float4 d4 = make_float4(jbase, jbase + 1.f, jbase + 2.f, jbase + 3.f);

#pragma unroll
    for (int r = 0; r < 4; r++) {
        const int i  = i0 + ty * 4 + r;
        const float si = sqi[ty * 4 + r];
        const float iv = (float)(gb + i);
        const size_t rowoff = (size_t)g * ((size_t)N_PER * N_PER)
                            + (size_t)i * N_PER + j0 + tx * 4;
        float d0 = fmaxf(si + s0 - 2.0f * acc[r][0], 0.0f);
        float d1 = fmaxf(si + s1 - 2.0f * acc[r][1], 0.0f);
        float d2 = fmaxf(si + s2 - 2.0f * acc[r][2], 0.0f);
        float d3 = fmaxf(si + s3 - 2.0f * acc[r][3], 0.0f);
        float4 w;
        w.x = 1.0f / (1.0f + __expf(-T * (th - d0)));
        w.y = 1.0f / (1.0f + __expf(-T * (th - d1)));
        w.z = 1.0f / (1.0f + __expf(-T * (th - d2)));
        w.w = 1.0f / (1.0f + __expf(-T * (th - d3)));
        *(float4*)&out[OFF_SRC + rowoff] = make_float4(iv, iv, iv, iv);
        *(float4*)&out[OFF_DST + rowoff] = d4;
        *(float4*)&out[OFF_W   + rowoff] = w;
    }
}

// ---------------------------------------------------------------------------
// Launch
// ---------------------------------------------------------------------------
extern "C" void kernel_launch(void* const* d_in, const int* in_sizes, int n_in,
                              void* d_out, int out_size) {
    const float* x    = (const float*)d_in[0];
    const float* W    = (const float*)d_in[1];
    const float* temp = (const float*)d_in[2];
    const float* thr  = (const float*)d_in[3];
    float* out = (float*)d_out;

    k_gemm <<<N_TOTAL / 32, 256>>>(x, W, out);
    k_stats<<<1, 1024>>>(out);
    k_norm <<<N_TOTAL / 8, 256>>>(out);
    k_pair <<<dim3(N_PER / BN, N_PER / BM, G_NUM), 256>>>(temp, thr, out);
}